// round 1
// baseline (speedup 1.0000x reference)
#include <cuda_runtime.h>
#include <math.h>

// ---------------- problem constants ----------------
#define BATCH   8
#define CIN     64
#define CDIM    192
#define HDIM    112
#define WDIM    112
#define L       (HDIM*WDIM)          // 12544
#define TKN     (BATCH*L)            // 100352
#define WS      7
#define NWIN    49
#define NH      6
#define HD      32
#define NWTOT   (BATCH*16*16)        // 2048 windows

// ---------------- scratch (static device; no dynamic alloc allowed) ----------------
__device__ float g_xt [TKN*CDIM];    // conv output, token-major [T,192]  (also the shortcut)
__device__ float g_xn [TKN*CDIM];    // LN output (reused for ln1 and ln2)
__device__ float g_qkv[TKN*3*CDIM];  // [T,576]
__device__ float g_ao [TKN*CDIM];    // attention output [T,192]
__device__ float g_t1 [TKN*CDIM];    // after attn residual
__device__ float g_m1 [TKN*4*CDIM];  // fc1+gelu [T,768]
__device__ float g_t2 [TKN*CDIM];    // after mlp residual

// ---------------- generic tiled SGEMM: C[m,n] = A[m,:]·W[n,:] + bias[n] (+epilogue) ----------------
// BM=128, BN=64, BK=16, 256 threads, each thread 8x4 micro-tile.
// EPI: 0 = bias only, 1 = bias + residual, 2 = bias + exact GELU
template<int EPI>
__global__ __launch_bounds__(256) void gemm_tn(const float* __restrict__ A,
                                               const float* __restrict__ W,
                                               const float* __restrict__ bias,
                                               const float* __restrict__ res,
                                               float* __restrict__ C,
                                               int N, int K)
{
    __shared__ float As[16][128];
    __shared__ float Bs[16][64];
    const int t  = threadIdx.x;
    const int m0 = blockIdx.x * 128;
    const int n0 = blockIdx.y * 64;
    const int tr = t >> 4;            // 0..15 -> rows tr*8..tr*8+7
    const int tc = t & 15;            // 0..15 -> cols tc*4..tc*4+3
    const int brow = t >> 2;          // 0..63 (B-tile row)
    const int bseg = t & 3;

    float acc[8][4];
    #pragma unroll
    for (int i = 0; i < 8; i++)
        #pragma unroll
        for (int j = 0; j < 4; j++) acc[i][j] = 0.f;

    for (int k0 = 0; k0 < K; k0 += 16) {
        // A tile: 128x16 = 512 float4, 2 per thread
        #pragma unroll
        for (int l = 0; l < 2; l++) {
            int id  = t + l*256;
            int row = id >> 2;
            int seg = id & 3;
            float4 a = *(const float4*)(A + (size_t)(m0+row)*K + k0 + seg*4);
            As[seg*4+0][row] = a.x; As[seg*4+1][row] = a.y;
            As[seg*4+2][row] = a.z; As[seg*4+3][row] = a.w;
        }
        // B tile: 64x16 = 256 float4, 1 per thread
        {
            float4 b = *(const float4*)(W + (size_t)(n0+brow)*K + k0 + bseg*4);
            Bs[bseg*4+0][brow] = b.x; Bs[bseg*4+1][brow] = b.y;
            Bs[bseg*4+2][brow] = b.z; Bs[bseg*4+3][brow] = b.w;
        }
        __syncthreads();
        #pragma unroll
        for (int kk = 0; kk < 16; kk++) {
            float4 a0 = *(const float4*)&As[kk][tr*8];
            float4 a1 = *(const float4*)&As[kk][tr*8+4];
            float4 bv = *(const float4*)&Bs[kk][tc*4];
            float av[8] = {a0.x,a0.y,a0.z,a0.w,a1.x,a1.y,a1.z,a1.w};
            float bw[4] = {bv.x,bv.y,bv.z,bv.w};
            #pragma unroll
            for (int i = 0; i < 8; i++)
                #pragma unroll
                for (int j = 0; j < 4; j++)
                    acc[i][j] += av[i]*bw[j];
        }
        __syncthreads();
    }

    #pragma unroll
    for (int i = 0; i < 8; i++) {
        int m = m0 + tr*8 + i;
        #pragma unroll
        for (int j = 0; j < 4; j++) {
            int n = n0 + tc*4 + j;
            float v = acc[i][j] + bias[n];
            if (EPI == 1) v += res[(size_t)m*N + n];
            if (EPI == 2) v = 0.5f*v*(1.0f + erff(v*0.70710678118654752f));
            C[(size_t)m*N + n] = v;
        }
    }
}

// ---------------- implicit-GEMM conv 3x3 SAME: x[8,64,112,112] -> g_xt[T,192] ----------------
__global__ __launch_bounds__(256) void conv_gemm(const float* __restrict__ x,
                                                 const float* __restrict__ W,
                                                 const float* __restrict__ bias,
                                                 float* __restrict__ C)
{
    // M=100352, N=192, K=576 (k = ci*9 + kh*3 + kw, matches OIHW weight layout)
    __shared__ float As[16][128];
    __shared__ float Bs[16][64];
    const int t  = threadIdx.x;
    const int m0 = blockIdx.x * 128;
    const int n0 = blockIdx.y * 64;
    const int tr = t >> 4, tc = t & 15;
    const int brow = t >> 2, bseg = t & 3;

    // im2col row owned by this thread (constant across loop since 256 % 128 == 0)
    const int ml = t & 127;
    const int kb = t >> 7;            // 0 or 1
    const int mm = m0 + ml;
    const int b  = mm / L;
    const int hw = mm % L;
    const int h  = hw / WDIM;
    const int w  = hw % WDIM;

    float acc[8][4];
    #pragma unroll
    for (int i = 0; i < 8; i++)
        #pragma unroll
        for (int j = 0; j < 4; j++) acc[i][j] = 0.f;

    for (int k0 = 0; k0 < 576; k0 += 16) {
        #pragma unroll
        for (int l = 0; l < 8; l++) {
            int kl = kb + l*2;
            int k  = k0 + kl;
            int ci = k / 9, r = k % 9;
            int kh = r / 3, kw = r % 3;
            int ih = h + kh - 1, iw = w + kw - 1;
            float v = 0.f;
            if (ih >= 0 && ih < HDIM && iw >= 0 && iw < WDIM)
                v = x[((b*CIN + ci)*HDIM + ih)*WDIM + iw];
            As[kl][ml] = v;
        }
        {
            float4 bv = *(const float4*)(W + (n0+brow)*576 + k0 + bseg*4);
            Bs[bseg*4+0][brow] = bv.x; Bs[bseg*4+1][brow] = bv.y;
            Bs[bseg*4+2][brow] = bv.z; Bs[bseg*4+3][brow] = bv.w;
        }
        __syncthreads();
        #pragma unroll
        for (int kk = 0; kk < 16; kk++) {
            float4 a0 = *(const float4*)&As[kk][tr*8];
            float4 a1 = *(const float4*)&As[kk][tr*8+4];
            float4 bv = *(const float4*)&Bs[kk][tc*4];
            float av[8] = {a0.x,a0.y,a0.z,a0.w,a1.x,a1.y,a1.z,a1.w};
            float bw[4] = {bv.x,bv.y,bv.z,bv.w};
            #pragma unroll
            for (int i = 0; i < 8; i++)
                #pragma unroll
                for (int j = 0; j < 4; j++)
                    acc[i][j] += av[i]*bw[j];
        }
        __syncthreads();
    }

    #pragma unroll
    for (int i = 0; i < 8; i++) {
        int m = m0 + tr*8 + i;
        #pragma unroll
        for (int j = 0; j < 4; j++) {
            int n = n0 + tc*4 + j;
            C[(size_t)m*CDIM + n] = acc[i][j] + bias[n];
        }
    }
}

// ---------------- LayerNorm over C=192 (one warp per token, 6 elems/lane) ----------------
__global__ __launch_bounds__(128) void ln_kernel(const float* __restrict__ in,
                                                 const float* __restrict__ w,
                                                 const float* __restrict__ b,
                                                 float* __restrict__ out)
{
    int warp = (blockIdx.x * blockDim.x + threadIdx.x) >> 5;
    int lane = threadIdx.x & 31;
    if (warp >= TKN) return;
    const float* p = in + (size_t)warp*CDIM;
    float v[6];
    float s = 0.f;
    #pragma unroll
    for (int j = 0; j < 6; j++) { v[j] = p[lane + 32*j]; s += v[j]; }
    #pragma unroll
    for (int o = 16; o > 0; o >>= 1) s += __shfl_xor_sync(0xffffffffu, s, o);
    float mu = s * (1.f/CDIM);
    float q = 0.f;
    #pragma unroll
    for (int j = 0; j < 6; j++) { float d = v[j]-mu; q += d*d; }
    #pragma unroll
    for (int o = 16; o > 0; o >>= 1) q += __shfl_xor_sync(0xffffffffu, q, o);
    float rs = rsqrtf(q * (1.f/CDIM) + 1e-5f);
    float* po = out + (size_t)warp*CDIM;
    #pragma unroll
    for (int j = 0; j < 6; j++) {
        int c = lane + 32*j;
        po[c] = (v[j]-mu)*rs*w[c] + b[c];
    }
}

// ---------------- window attention: one block per (window, head) ----------------
__global__ __launch_bounds__(256) void attn_kernel(const float* __restrict__ qkv,
                                                   const float* __restrict__ rel_table,
                                                   const int*   __restrict__ rel_index,
                                                   float* __restrict__ o)
{
    const int wi   = blockIdx.x;     // 0..2047
    const int head = blockIdx.y;     // 0..5
    __shared__ float qs[NWIN][33], ks[NWIN][33], vs[NWIN][HD];
    __shared__ float sc[NWIN*NWIN];
    __shared__ int   toks[NWIN];
    const int t = threadIdx.x;

    const int b  = wi >> 8;
    const int r  = wi & 255;
    const int wh = r >> 4, ww = r & 15;
    if (t < NWIN) {
        int ph = t / WS, pw = t % WS;
        toks[t] = b*L + (wh*WS+ph)*WDIM + (ww*WS+pw);
    }
    __syncthreads();

    for (int idx = t; idx < NWIN*HD; idx += 256) {
        int p = idx >> 5, d = idx & 31;
        int base = toks[p]*(3*CDIM) + head*HD + d;
        qs[p][d] = qkv[base] * 0.17677669529663687f;   // HD^-0.5
        ks[p][d] = qkv[base + CDIM];
        vs[p][d] = qkv[base + 2*CDIM];
    }
    __syncthreads();

    for (int idx = t; idx < NWIN*NWIN; idx += 256) {
        int i = idx / NWIN, j = idx % NWIN;
        float dot = 0.f;
        #pragma unroll
        for (int d = 0; d < HD; d++) dot += qs[i][d]*ks[j][d];
        sc[idx] = dot + rel_table[rel_index[idx]*NH + head];
    }
    __syncthreads();

    if (t < NWIN) {
        float* row = &sc[t*NWIN];
        float mx = -1e30f;
        for (int j = 0; j < NWIN; j++) mx = fmaxf(mx, row[j]);
        float s = 0.f;
        for (int j = 0; j < NWIN; j++) { float e = expf(row[j]-mx); row[j] = e; s += e; }
        float inv = 1.f/s;
        for (int j = 0; j < NWIN; j++) row[j] *= inv;
    }
    __syncthreads();

    for (int idx = t; idx < NWIN*HD; idx += 256) {
        int i = idx >> 5, d = idx & 31;
        float acc = 0.f;
        #pragma unroll
        for (int j = 0; j < NWIN; j++) acc += sc[i*NWIN+j]*vs[j][d];
        o[(size_t)toks[i]*CDIM + head*HD + d] = acc;
    }
}

// ---------------- final: out[b,c,h,w] = t2[token,c] + conv_shortcut[token,c] ----------------
__global__ void out_add(const float* __restrict__ t2, const float* __restrict__ scut,
                        float* __restrict__ out)
{
    __shared__ float tile[32][33];
    const int b   = blockIdx.z;
    const int hw0 = blockIdx.x * 32;
    const int c0  = blockIdx.y * 32;
    const int tx  = threadIdx.x, ty = threadIdx.y;   // (32, 8)
    #pragma unroll
    for (int r = 0; r < 4; r++) {
        int i = r*8 + ty;
        size_t off = (size_t)(b*L + hw0 + i)*CDIM + c0 + tx;
        tile[i][tx] = t2[off] + scut[off];
    }
    __syncthreads();
    #pragma unroll
    for (int r = 0; r < 4; r++) {
        int cy = r*8 + ty;
        out[(size_t)(b*CDIM + c0 + cy)*L + hw0 + tx] = tile[tx][cy];
    }
}

// ---------------- launch ----------------
extern "C" void kernel_launch(void* const* d_in, const int* in_sizes, int n_in,
                              void* d_out, int out_size)
{
    const float* x        = (const float*)d_in[0];
    const float* proj_w   = (const float*)d_in[1];
    const float* proj_b   = (const float*)d_in[2];
    const float* ln1_w    = (const float*)d_in[3];
    const float* ln1_b    = (const float*)d_in[4];
    const float* qkv_w    = (const float*)d_in[5];
    const float* qkv_b    = (const float*)d_in[6];
    const float* rel_tab  = (const float*)d_in[7];
    const float* apw      = (const float*)d_in[8];
    const float* apb      = (const float*)d_in[9];
    const float* ln2_w    = (const float*)d_in[10];
    const float* ln2_b    = (const float*)d_in[11];
    const float* fc1_w    = (const float*)d_in[12];
    const float* fc1_b    = (const float*)d_in[13];
    const float* fc2_w    = (const float*)d_in[14];
    const float* fc2_b    = (const float*)d_in[15];
    const int*   rel_idx  = (const int*)d_in[16];
    float* out = (float*)d_out;

    float *xt, *xn, *qkv, *ao, *t1, *m1, *t2;
    cudaGetSymbolAddress((void**)&xt,  g_xt);
    cudaGetSymbolAddress((void**)&xn,  g_xn);
    cudaGetSymbolAddress((void**)&qkv, g_qkv);
    cudaGetSymbolAddress((void**)&ao,  g_ao);
    cudaGetSymbolAddress((void**)&t1,  g_t1);
    cudaGetSymbolAddress((void**)&m1,  g_m1);
    cudaGetSymbolAddress((void**)&t2,  g_t2);

    const int MB = TKN/128;   // 784

    // conv proj (implicit GEMM) -> token-major shortcut/input
    conv_gemm<<<dim3(MB,3), 256>>>(x, proj_w, proj_b, xt);
    // LN1
    ln_kernel<<<TKN/4, 128>>>(xt, ln1_w, ln1_b, xn);
    // qkv projection
    gemm_tn<0><<<dim3(MB,9), 256>>>(xn, qkv_w, qkv_b, nullptr, qkv, 3*CDIM, CDIM);
    // window attention
    attn_kernel<<<dim3(NWTOT,NH), 256>>>(qkv, rel_tab, rel_idx, ao);
    // attn out projection + residual(xt)
    gemm_tn<1><<<dim3(MB,3), 256>>>(ao, apw, apb, xt, t1, CDIM, CDIM);
    // LN2
    ln_kernel<<<TKN/4, 128>>>(t1, ln2_w, ln2_b, xn);
    // fc1 + exact GELU
    gemm_tn<2><<<dim3(MB,12), 256>>>(xn, fc1_w, fc1_b, nullptr, m1, 4*CDIM, CDIM);
    // fc2 + residual(t1)
    gemm_tn<1><<<dim3(MB,3), 256>>>(m1, fc2_w, fc2_b, t1, t2, CDIM, 4*CDIM);
    // transpose to NCHW + conv shortcut
    out_add<<<dim3(L/32, CDIM/32, BATCH), dim3(32,8)>>>(t2, xt, out);
}

// round 2
// speedup vs baseline: 1.1882x; 1.1882x over previous
#include <cuda_runtime.h>
#include <math.h>

// ---------------- problem constants ----------------
#define BATCH   8
#define CIN     64
#define CDIM    192
#define HDIM    112
#define WDIM    112
#define L       (HDIM*WDIM)          // 12544
#define TKN     (BATCH*L)            // 100352
#define WS      7
#define NWIN    49
#define NH      6
#define HD      32
#define NWTOT   2048
#define KCONV   576

typedef unsigned long long u64;

// ---------------- f32x2 packed-FMA helpers (sm_103a FFMA2) ----------------
#define FMA2(d,a,b)    asm("fma.rn.f32x2 %0, %1, %2, %0;" : "+l"(d) : "l"(a), "l"(b))
#define PACK2(d,x)     asm("mov.b64 %0, {%1, %1};" : "=l"(d) : "f"(x))
#define PACK2XY(d,x,y) asm("mov.b64 %0, {%1, %2};" : "=l"(d) : "f"(x), "f"(y))
#define UNPACK2(x,y,d) asm("mov.b64 {%0, %1}, %2;" : "=f"(x), "=f"(y) : "l"(d))

// ---------------- scratch (static device; no dynamic alloc allowed) ----------------
__device__ float g_col [(size_t)TKN*KCONV];   // im2col for conv
__device__ float g_xt  [(size_t)TKN*CDIM];    // conv out, token-major (also shortcut)
__device__ float g_xn  [(size_t)TKN*CDIM];    // LN output
__device__ float g_qkv [(size_t)TKN*3*CDIM];
__device__ float g_ao  [(size_t)TKN*CDIM];
__device__ float g_t1  [(size_t)TKN*CDIM];
__device__ float g_m1  [(size_t)TKN*4*CDIM];
__device__ float g_t2  [(size_t)TKN*CDIM];
__device__ float g_bias[NH*NWIN*NWIN];

// ---------------- FFMA2 SGEMM: C[m,n] = A[m,:]·W[n,:] + bias (+epilogue) ----------------
// BM=128, BN=64, BK=16, 128 threads, 8x8 micro-tile as 8x4 f32x2 accumulators.
// EPI: 0 = bias, 1 = bias+residual, 2 = bias+exact GELU
template<int EPI>
__global__ __launch_bounds__(128,3) void gemm_tn(const float* __restrict__ A,
                                                 const float* __restrict__ W,
                                                 const float* __restrict__ bias,
                                                 const float* __restrict__ res,
                                                 float* __restrict__ C,
                                                 int N, int K)
{
    __shared__ float As[2][16][132];   // padded to kill STS bank conflicts
    __shared__ float Bs[2][16][68];
    const int t  = threadIdx.x;
    const int n0 = blockIdx.x * 64;
    const int m0 = blockIdx.y * 128;
    const int tr = t >> 3, tc = t & 7;        // 16 x 8 compute layout
    const int r4 = t >> 2, s4 = (t & 3) * 4;  // loader: row r4(+32l), k-cols s4..s4+3

    u64 acc[8][4];
    u64 z2; { float z = 0.f; PACK2(z2, z); }
    #pragma unroll
    for (int i = 0; i < 8; i++)
        #pragma unroll
        for (int j = 0; j < 4; j++) acc[i][j] = z2;

    const int nc = K >> 4;
    float4 ra[4], rb[2];

    // prefetch chunk 0 -> regs
    #pragma unroll
    for (int l = 0; l < 4; l++)
        ra[l] = *(const float4*)(A + (size_t)(m0 + r4 + l*32)*K + s4);
    #pragma unroll
    for (int l = 0; l < 2; l++)
        rb[l] = *(const float4*)(W + (size_t)(n0 + r4 + l*32)*K + s4);
    // store chunk 0 -> buf0
    #pragma unroll
    for (int l = 0; l < 4; l++) {
        As[0][s4+0][r4+l*32] = ra[l].x; As[0][s4+1][r4+l*32] = ra[l].y;
        As[0][s4+2][r4+l*32] = ra[l].z; As[0][s4+3][r4+l*32] = ra[l].w;
    }
    #pragma unroll
    for (int l = 0; l < 2; l++) {
        Bs[0][s4+0][r4+l*32] = rb[l].x; Bs[0][s4+1][r4+l*32] = rb[l].y;
        Bs[0][s4+2][r4+l*32] = rb[l].z; Bs[0][s4+3][r4+l*32] = rb[l].w;
    }
    // prefetch chunk 1 -> regs
    if (nc > 1) {
        #pragma unroll
        for (int l = 0; l < 4; l++)
            ra[l] = *(const float4*)(A + (size_t)(m0 + r4 + l*32)*K + 16 + s4);
        #pragma unroll
        for (int l = 0; l < 2; l++)
            rb[l] = *(const float4*)(W + (size_t)(n0 + r4 + l*32)*K + 16 + s4);
    }
    __syncthreads();

    for (int c = 0; c < nc; c++) {
        const int cur = c & 1, nxt = cur ^ 1;
        if (c + 1 < nc) {   // STS chunk c+1 into other buffer (safe: its readers done last sync)
            #pragma unroll
            for (int l = 0; l < 4; l++) {
                As[nxt][s4+0][r4+l*32] = ra[l].x; As[nxt][s4+1][r4+l*32] = ra[l].y;
                As[nxt][s4+2][r4+l*32] = ra[l].z; As[nxt][s4+3][r4+l*32] = ra[l].w;
            }
            #pragma unroll
            for (int l = 0; l < 2; l++) {
                Bs[nxt][s4+0][r4+l*32] = rb[l].x; Bs[nxt][s4+1][r4+l*32] = rb[l].y;
                Bs[nxt][s4+2][r4+l*32] = rb[l].z; Bs[nxt][s4+3][r4+l*32] = rb[l].w;
            }
        }
        if (c + 2 < nc) {   // LDG chunk c+2 -> regs
            const int k0 = (c + 2) * 16;
            #pragma unroll
            for (int l = 0; l < 4; l++)
                ra[l] = *(const float4*)(A + (size_t)(m0 + r4 + l*32)*K + k0 + s4);
            #pragma unroll
            for (int l = 0; l < 2; l++)
                rb[l] = *(const float4*)(W + (size_t)(n0 + r4 + l*32)*K + k0 + s4);
        }
        #pragma unroll
        for (int kk = 0; kk < 16; kk++) {
            float4 a0 = *(const float4*)&As[cur][kk][tr*8];
            float4 a1 = *(const float4*)&As[cur][kk][tr*8+4];
            u64 bv0 = *(const u64*)&Bs[cur][kk][tc*8];
            u64 bv1 = *(const u64*)&Bs[cur][kk][tc*8+2];
            u64 bv2 = *(const u64*)&Bs[cur][kk][tc*8+4];
            u64 bv3 = *(const u64*)&Bs[cur][kk][tc*8+6];
            u64 av[8];
            PACK2(av[0],a0.x); PACK2(av[1],a0.y); PACK2(av[2],a0.z); PACK2(av[3],a0.w);
            PACK2(av[4],a1.x); PACK2(av[5],a1.y); PACK2(av[6],a1.z); PACK2(av[7],a1.w);
            #pragma unroll
            for (int i = 0; i < 8; i++) {
                FMA2(acc[i][0], av[i], bv0);
                FMA2(acc[i][1], av[i], bv1);
                FMA2(acc[i][2], av[i], bv2);
                FMA2(acc[i][3], av[i], bv3);
            }
        }
        __syncthreads();
    }

    // epilogue
    const float4 bb0 = *(const float4*)(bias + n0 + tc*8);
    const float4 bb1 = *(const float4*)(bias + n0 + tc*8 + 4);
    #pragma unroll
    for (int i = 0; i < 8; i++) {
        const int m = m0 + tr*8 + i;
        float o[8];
        #pragma unroll
        for (int j = 0; j < 4; j++) UNPACK2(o[2*j], o[2*j+1], acc[i][j]);
        o[0]+=bb0.x; o[1]+=bb0.y; o[2]+=bb0.z; o[3]+=bb0.w;
        o[4]+=bb1.x; o[5]+=bb1.y; o[6]+=bb1.z; o[7]+=bb1.w;
        if (EPI == 1) {
            float4 r0 = *(const float4*)(res + (size_t)m*N + n0 + tc*8);
            float4 r1 = *(const float4*)(res + (size_t)m*N + n0 + tc*8 + 4);
            o[0]+=r0.x; o[1]+=r0.y; o[2]+=r0.z; o[3]+=r0.w;
            o[4]+=r1.x; o[5]+=r1.y; o[6]+=r1.z; o[7]+=r1.w;
        }
        if (EPI == 2) {
            #pragma unroll
            for (int j = 0; j < 8; j++)
                o[j] = 0.5f*o[j]*(1.0f + erff(o[j]*0.70710678118654752f));
        }
        *(float4*)(C + (size_t)m*N + n0 + tc*8)     = make_float4(o[0],o[1],o[2],o[3]);
        *(float4*)(C + (size_t)m*N + n0 + tc*8 + 4) = make_float4(o[4],o[5],o[6],o[7]);
    }
}

// ---------------- im2col for conv: col[m, ci*9+kh*3+kw] ----------------
__global__ void im2col_k(const float* __restrict__ x, float* __restrict__ col)
{
    size_t i4 = (size_t)blockIdx.x*256 + threadIdx.x;   // TKN*144 float4s
    if (i4 >= (size_t)TKN*144) return;
    int m  = (int)(i4 / 144);
    int k0 = (int)(i4 % 144) * 4;
    int b = m / L, hw = m % L, h = hw / WDIM, w = hw % WDIM;
    float v[4];
    #pragma unroll
    for (int u = 0; u < 4; u++) {
        int k = k0 + u, ci = k / 9, rr = k - ci*9, kh = rr / 3, kw = rr - kh*3;
        int ih = h + kh - 1, iw = w + kw - 1;
        v[u] = (ih >= 0 && ih < HDIM && iw >= 0 && iw < WDIM)
             ? x[((size_t)(b*CIN + ci)*HDIM + ih)*WDIM + iw] : 0.f;
    }
    *(float4*)&col[(size_t)m*KCONV + k0] = make_float4(v[0],v[1],v[2],v[3]);
}

// ---------------- rel-pos bias precompute: g_bias[head][i][j] ----------------
__global__ void bias_pre(const float* __restrict__ tab, const int* __restrict__ idx,
                         float* __restrict__ out)
{
    int i = blockIdx.x*256 + threadIdx.x;
    if (i < NH*NWIN*NWIN) {
        int h = i / (NWIN*NWIN), ij = i % (NWIN*NWIN);
        out[i] = tab[idx[ij]*NH + h];
    }
}

// ---------------- LayerNorm over C=192 (one warp per token) ----------------
__global__ __launch_bounds__(128) void ln_kernel(const float* __restrict__ in,
                                                 const float* __restrict__ w,
                                                 const float* __restrict__ b,
                                                 float* __restrict__ out)
{
    int warp = (blockIdx.x * blockDim.x + threadIdx.x) >> 5;
    int lane = threadIdx.x & 31;
    if (warp >= TKN) return;
    const float* p = in + (size_t)warp*CDIM;
    float v[6];
    float s = 0.f;
    #pragma unroll
    for (int j = 0; j < 6; j++) { v[j] = p[lane + 32*j]; s += v[j]; }
    #pragma unroll
    for (int o = 16; o > 0; o >>= 1) s += __shfl_xor_sync(0xffffffffu, s, o);
    float mu = s * (1.f/CDIM);
    float q = 0.f;
    #pragma unroll
    for (int j = 0; j < 6; j++) { float d = v[j]-mu; q += d*d; }
    #pragma unroll
    for (int o = 16; o > 0; o >>= 1) q += __shfl_xor_sync(0xffffffffu, q, o);
    float rs = rsqrtf(q * (1.f/CDIM) + 1e-5f);
    float* po = out + (size_t)warp*CDIM;
    #pragma unroll
    for (int j = 0; j < 6; j++) {
        int c = lane + 32*j;
        po[c] = (v[j]-mu)*rs*w[c] + b[c];
    }
}

// ---------------- window attention: block = (window, head), 64 threads ----------------
__global__ __launch_bounds__(64) void attn_kernel(const float* __restrict__ qkv,
                                                  const float* __restrict__ biasg,
                                                  float* __restrict__ o)
{
    __shared__ float ks[NWIN*HD], vs[NWIN*HD];
    __shared__ float sc[NWIN*NWIN];
    __shared__ int toks[NWIN];
    const int t = threadIdx.x;
    const int wi = blockIdx.x, head = blockIdx.y;
    const int b = wi >> 8, r = wi & 255, wh = r >> 4, ww = r & 15;
    if (t < NWIN) toks[t] = b*L + (wh*WS + t/WS)*WDIM + (ww*WS + t%WS);
    __syncthreads();

    for (int idx = t; idx < NWIN*8; idx += 64) {
        int row = idx >> 3, seg = idx & 7;
        const float4* src = (const float4*)(qkv + (size_t)toks[row]*(3*CDIM) + head*HD);
        *(float4*)&ks[row*HD + seg*4] = src[seg + 48];   // K at +192 floats
        *(float4*)&vs[row*HD + seg*4] = src[seg + 96];   // V at +384 floats
    }
    u64 q2[16];
    if (t < NWIN) {
        const float4* src = (const float4*)(qkv + (size_t)toks[t]*(3*CDIM) + head*HD);
        const float s = 0.17677669529663687f;   // HD^-0.5
        #pragma unroll
        for (int l = 0; l < 8; l++) {
            float4 f = src[l];
            PACK2XY(q2[2*l],   f.x*s, f.y*s);
            PACK2XY(q2[2*l+1], f.z*s, f.w*s);
        }
    }
    __syncthreads();

    if (t < NWIN) {
        u64 z2; { float z = 0.f; PACK2(z2, z); }
        const float* bs = biasg + head*(NWIN*NWIN) + t*NWIN;
        float* row = &sc[t*NWIN];
        // Q@K^T row (K broadcast-loaded from smem, Q in regs)
        for (int j = 0; j < NWIN; j++) {
            u64 a2 = z2;
            #pragma unroll
            for (int d = 0; d < 16; d++)
                FMA2(a2, q2[d], *(const u64*)&ks[j*HD + 2*d]);
            float lo, hi; UNPACK2(lo, hi, a2);
            row[j] = lo + hi + bs[j];
        }
        // softmax (thread-local row)
        float mx = -1e30f;
        for (int j = 0; j < NWIN; j++) mx = fmaxf(mx, row[j]);
        float s = 0.f;
        for (int j = 0; j < NWIN; j++) { float e = expf(row[j]-mx); row[j] = e; s += e; }
        float inv = 1.f/s;
        // P@V
        u64 acc2[16];
        #pragma unroll
        for (int d = 0; d < 16; d++) acc2[d] = z2;
        for (int j = 0; j < NWIN; j++) {
            u64 p2; float p = row[j]*inv; PACK2(p2, p);
            #pragma unroll
            for (int d = 0; d < 16; d++)
                FMA2(acc2[d], p2, *(const u64*)&vs[j*HD + 2*d]);
        }
        float* dst = o + (size_t)toks[t]*CDIM + head*HD;
        #pragma unroll
        for (int l = 0; l < 8; l++) {
            float x0,x1,x2,x3;
            UNPACK2(x0,x1,acc2[2*l]); UNPACK2(x2,x3,acc2[2*l+1]);
            *(float4*)(dst + l*4) = make_float4(x0,x1,x2,x3);
        }
    }
}

// ---------------- final: out[b,c,h,w] = t2[tok,c] + shortcut[tok,c] (transpose) --------
__global__ void out_add(const float* __restrict__ t2, const float* __restrict__ scut,
                        float* __restrict__ out)
{
    __shared__ float tile[32][33];
    const int b   = blockIdx.z;
    const int hw0 = blockIdx.x * 32;
    const int c0  = blockIdx.y * 32;
    const int tx  = threadIdx.x, ty = threadIdx.y;   // (32, 8)
    #pragma unroll
    for (int r = 0; r < 4; r++) {
        int i = r*8 + ty;
        size_t off = (size_t)(b*L + hw0 + i)*CDIM + c0 + tx;
        tile[i][tx] = t2[off] + scut[off];
    }
    __syncthreads();
    #pragma unroll
    for (int r = 0; r < 4; r++) {
        int cy = r*8 + ty;
        out[(size_t)(b*CDIM + c0 + cy)*L + hw0 + tx] = tile[tx][cy];
    }
}

// ---------------- launch ----------------
extern "C" void kernel_launch(void* const* d_in, const int* in_sizes, int n_in,
                              void* d_out, int out_size)
{
    const float* x        = (const float*)d_in[0];
    const float* proj_w   = (const float*)d_in[1];
    const float* proj_b   = (const float*)d_in[2];
    const float* ln1_w    = (const float*)d_in[3];
    const float* ln1_b    = (const float*)d_in[4];
    const float* qkv_w    = (const float*)d_in[5];
    const float* qkv_b    = (const float*)d_in[6];
    const float* rel_tab  = (const float*)d_in[7];
    const float* apw      = (const float*)d_in[8];
    const float* apb      = (const float*)d_in[9];
    const float* ln2_w    = (const float*)d_in[10];
    const float* ln2_b    = (const float*)d_in[11];
    const float* fc1_w    = (const float*)d_in[12];
    const float* fc1_b    = (const float*)d_in[13];
    const float* fc2_w    = (const float*)d_in[14];
    const float* fc2_b    = (const float*)d_in[15];
    const int*   rel_idx  = (const int*)d_in[16];
    float* out = (float*)d_out;

    float *col, *xt, *xn, *qkvb, *ao, *t1, *m1, *t2, *biasp;
    cudaGetSymbolAddress((void**)&col,   g_col);
    cudaGetSymbolAddress((void**)&xt,    g_xt);
    cudaGetSymbolAddress((void**)&xn,    g_xn);
    cudaGetSymbolAddress((void**)&qkvb,  g_qkv);
    cudaGetSymbolAddress((void**)&ao,    g_ao);
    cudaGetSymbolAddress((void**)&t1,    g_t1);
    cudaGetSymbolAddress((void**)&m1,    g_m1);
    cudaGetSymbolAddress((void**)&t2,    g_t2);
    cudaGetSymbolAddress((void**)&biasp, g_bias);

    const int MB = TKN/128;   // 784

    bias_pre<<<57, 256>>>(rel_tab, rel_idx, biasp);
    im2col_k<<<(int)(((size_t)TKN*144 + 255)/256), 256>>>(x, col);
    // conv as GEMM on im2col
    gemm_tn<0><<<dim3(3, MB), 128>>>(col, proj_w, proj_b, nullptr, xt, CDIM, KCONV);
    ln_kernel<<<TKN/4, 128>>>(xt, ln1_w, ln1_b, xn);
    gemm_tn<0><<<dim3(9, MB), 128>>>(xn, qkv_w, qkv_b, nullptr, qkvb, 3*CDIM, CDIM);
    attn_kernel<<<dim3(NWTOT, NH), 64>>>(qkvb, biasp, ao);
    gemm_tn<1><<<dim3(3, MB), 128>>>(ao, apw, apb, xt, t1, CDIM, CDIM);
    ln_kernel<<<TKN/4, 128>>>(t1, ln2_w, ln2_b, xn);
    gemm_tn<2><<<dim3(12, MB), 128>>>(xn, fc1_w, fc1_b, nullptr, m1, 4*CDIM, CDIM);
    gemm_tn<1><<<dim3(3, MB), 128>>>(m1, fc2_w, fc2_b, t1, t2, CDIM, 4*CDIM);
    out_add<<<dim3(L/32, CDIM/32, BATCH), dim3(32,8)>>>(t2, xt, out);
}